// round 14
// baseline (speedup 1.0000x reference)
#include <cuda_runtime.h>
#include <cuda_fp16.h>
#include <cstdint>

// ============ helpers ============

__device__ __forceinline__ uint32_t smem_u32(const void* p) {
    uint32_t a;
    asm("{ .reg .u64 t; cvta.to.shared.u64 t, %1; cvt.u32.u64 %0, t; }" : "=r"(a) : "l"(p));
    return a;
}

__device__ __forceinline__ void cp_async16(uint32_t saddr, const void* gaddr) {
    asm volatile("cp.async.cg.shared.global [%0], [%1], 16;" :: "r"(saddr), "l"(gaddr));
}
#define CP_COMMIT() asm volatile("cp.async.commit_group;" ::: "memory")
#define CP_WAIT(N)  asm volatile("cp.async.wait_group %0;" :: "n"(N) : "memory")

__device__ __forceinline__ void ldsm_x4(uint32_t addr, uint32_t& r0, uint32_t& r1,
                                        uint32_t& r2, uint32_t& r3) {
    asm volatile("ldmatrix.sync.aligned.m8n8.x4.shared.b16 {%0,%1,%2,%3}, [%4];"
                 : "=r"(r0), "=r"(r1), "=r"(r2), "=r"(r3) : "r"(addr));
}

__device__ __forceinline__ void lds128(uint32_t addr, uint32_t& x, uint32_t& y,
                                       uint32_t& z, uint32_t& w) {
    asm volatile("ld.shared.v4.b32 {%0,%1,%2,%3}, [%4];"
                 : "=r"(x), "=r"(y), "=r"(z), "=r"(w) : "r"(addr));
}
__device__ __forceinline__ void sts128(uint32_t a, uint32_t x, uint32_t y, uint32_t z, uint32_t w) {
    asm volatile("st.shared.v4.b32 [%0], {%1,%2,%3,%4};"
                 :: "r"(a), "r"(x), "r"(y), "r"(z), "r"(w) : "memory");
}

__device__ __forceinline__ void mma16816(float* c, const uint32_t* a, uint32_t b0, uint32_t b1) {
    asm volatile(
        "mma.sync.aligned.m16n8k16.row.col.f32.f16.f16.f32 "
        "{%0,%1,%2,%3}, {%4,%5,%6,%7}, {%8,%9}, {%0,%1,%2,%3};"
        : "+f"(c[0]), "+f"(c[1]), "+f"(c[2]), "+f"(c[3])
        : "r"(a[0]), "r"(a[1]), "r"(a[2]), "r"(a[3]), "r"(b0), "r"(b1));
}

__device__ __forceinline__ void split2(float v0, float v1, uint32_t& hi, uint32_t& lo) {
    __half h0 = __float2half_rn(v0), h1 = __float2half_rn(v1);
    __half2 hh = __halves2half2(h0, h1);
    hi = *(uint32_t*)&hh;
    __half2 ll = __floats2half2_rn(v0 - __half2float(h0), v1 - __half2float(h1));
    lo = *(uint32_t*)&ll;
}

// ============ device scratch ============

static constexpr size_t NEL = 16ull * 1024 * 1024;  // 16 x 1024 x 1024

__device__ __half g_w[NEL];     // softmax weights, fp16
__device__ __half g_et[NEL];    // E^T per batch, fp16: [b][d][k]
__device__ float  g_scores[NEL];

// ---- GEMM1 smem layout (k32, single staging, DOUBLE swizzled fp16 tiles) ----
static constexpr int G1_ROW32 = 144;                 // fp32 staging row stride
static constexpr int G1_STG   = 128 * G1_ROW32;      // 18432 B per operand
static constexpr int G1_SA    = 0;
static constexpr int G1_SB    = G1_STG;
static constexpr int G1_TB    = 2 * G1_STG;          // 36864: tiles base
static constexpr int G1_TSZ   = 128 * 64;            // 8192: 64B rows, XOR-swizzled
static constexpr int G1_STAGE = 4 * G1_TSZ;          // 32768: QH,QL,EH,EL
static constexpr int G1_SMEM  = G1_TB + 2 * G1_STAGE;  // 102400 B

// ---- GEMM2 smem layout (k64, 3-slot rotation; R10-proven) ----
static constexpr int G2_ROW  = 144;
static constexpr int G2_TILE = 128 * G2_ROW;         // 18432 B per operand
static constexpr int G2_SMEM = 3 * 2 * G2_TILE;      // 110592 B

// ============ GEMM1: scores = Q @ E^T, single-sync overlap pipeline ============
// CTA 128x128, 8 warps (2M x 4N), k32, MMA lags convert by one chunk, 2 CTAs/SM.
// Per-thread cp region == its convert region (program-order race freedom).

__device__ __forceinline__ void g1_cp(uint32_t sb, int cm, int ck, int kc,
                                      const float* gQ, const float* gE) {
    uint32_t off = cm * G1_ROW32 + ck * 4;
    size_t go = (size_t)cm * 1024 + kc * 32 + ck;
    #pragma unroll
    for (int j = 0; j < 4; j++) {
        cp_async16(sb + G1_SA + off + j * 16, gQ + go + j * 4);
        cp_async16(sb + G1_SB + off + j * 16, gE + go + j * 4);
    }
    CP_COMMIT();
}

__global__ void __launch_bounds__(256, 2)
gemm1_kernel(const float* __restrict__ Q, const float* __restrict__ E) {
    extern __shared__ char smem[];
    uint32_t sb = smem_u32(smem);
    int tid = threadIdx.x, wid = tid >> 5, lane = tid & 31;
    int wm = wid >> 2, wn = wid & 3;
    int b = blockIdx.z;
    int m0 = blockIdx.y << 7, n0 = blockIdx.x << 7;
    size_t boff = (size_t)b << 20;

    const float* gQ = Q + boff + (size_t)m0 * 1024;
    const float* gE = E + boff + (size_t)n0 * 1024;

    float c[4][4][4];
    #pragma unroll
    for (int i = 0; i < 4; i++)
        #pragma unroll
        for (int j = 0; j < 4; j++)
            #pragma unroll
            for (int k = 0; k < 4; k++) c[i][j][k] = 0.f;

    // convert/cp per-thread mapping: row cm, 16-float half ck
    int cm = tid >> 1;
    int ck = (tid & 1) * 16;
    uint32_t csrc = cm * G1_ROW32 + ck * 4;
    // tile STS swizzle: row cm, segments s0c, s0c+1
    int fc = (cm >> 1) & 3;
    int s0c = (tid & 1) * 2;
    uint32_t cd0 = cm * 64 + (uint32_t)((s0c ^ fc) << 4);
    uint32_t cd1 = cm * 64 + (uint32_t)(((s0c + 1) ^ fc) << 4);

    // MMA-side swizzled k offsets (seg = ks*2 + (lane>>4), f = (lr>>1)&3)
    int lr = lane & 15;
    int fm = (lr >> 1) & 3;
    int seg0 = lane >> 4;
    uint32_t k0sw = (uint32_t)(((seg0 + 0) ^ fm) << 4);
    uint32_t k1sw = (uint32_t)(((seg0 + 2) ^ fm) << 4);

    g1_cp(sb, cm, ck, 0, gQ, gE);

    for (int kc = 0; kc <= 32; kc++) {
        if (kc < 32) {
            CP_WAIT(0);
            __syncthreads();   // S=chunk kc ready everywhere; T[kc&1] readers (MMA kc-2) done

            // ---- convert own S region -> T[kc&1] ----
            {
                uint32_t tb1 = sb + G1_TB + (kc & 1) * G1_STAGE;
                uint32_t ra[4][4], rb[4][4];
                #pragma unroll
                for (int j = 0; j < 4; j++)
                    lds128(sb + G1_SA + csrc + j * 16, ra[j][0], ra[j][1], ra[j][2], ra[j][3]);
                #pragma unroll
                for (int j = 0; j < 4; j++)
                    lds128(sb + G1_SB + csrc + j * 16, rb[j][0], rb[j][1], rb[j][2], rb[j][3]);

                uint32_t hi[8], lo[8];
                #pragma unroll
                for (int j = 0; j < 4; j++) {
                    split2(__uint_as_float(ra[j][0]), __uint_as_float(ra[j][1]), hi[j * 2], lo[j * 2]);
                    split2(__uint_as_float(ra[j][2]), __uint_as_float(ra[j][3]), hi[j * 2 + 1], lo[j * 2 + 1]);
                }
                sts128(tb1 + cd0,            hi[0], hi[1], hi[2], hi[3]);
                sts128(tb1 + cd1,            hi[4], hi[5], hi[6], hi[7]);
                sts128(tb1 + G1_TSZ + cd0,   lo[0], lo[1], lo[2], lo[3]);
                sts128(tb1 + G1_TSZ + cd1,   lo[4], lo[5], lo[6], lo[7]);
                #pragma unroll
                for (int j = 0; j < 4; j++) {
                    split2(__uint_as_float(rb[j][0]), __uint_as_float(rb[j][1]), hi[j * 2], lo[j * 2]);
                    split2(__uint_as_float(rb[j][2]), __uint_as_float(rb[j][3]), hi[j * 2 + 1], lo[j * 2 + 1]);
                }
                sts128(tb1 + 2 * G1_TSZ + cd0, hi[0], hi[1], hi[2], hi[3]);
                sts128(tb1 + 2 * G1_TSZ + cd1, hi[4], hi[5], hi[6], hi[7]);
                sts128(tb1 + 3 * G1_TSZ + cd0, lo[0], lo[1], lo[2], lo[3]);
                sts128(tb1 + 3 * G1_TSZ + cd1, lo[4], lo[5], lo[6], lo[7]);
            }

            // cp next chunk into OWN S region (safe: own LDS reads already retired)
            if (kc + 1 < 32) g1_cp(sb, cm, ck, kc + 1, gQ, gE);
        } else {
            __syncthreads();   // convert(31) complete everywhere
        }

        // ---- MMA on T[(kc-1)&1] (chunk kc-1) ----
        if (kc >= 1) {
            uint32_t tb = sb + G1_TB + ((kc - 1) & 1) * G1_STAGE;
            #pragma unroll
            for (int ks = 0; ks < 2; ks++) {
                uint32_t ksw = ks ? k1sw : k0sw;
                uint32_t bh[2][4], bl[2][4];
                #pragma unroll
                for (int p = 0; p < 2; p++) {
                    uint32_t a = tb + 2 * G1_TSZ + (wn * 32 + p * 16 + lr) * 64 + ksw;
                    ldsm_x4(a, bh[p][0], bh[p][1], bh[p][2], bh[p][3]);
                    ldsm_x4(a + G1_TSZ, bl[p][0], bl[p][1], bl[p][2], bl[p][3]);
                }
                #pragma unroll
                for (int mt = 0; mt < 4; mt++) {
                    uint32_t ah[4], al[4];
                    uint32_t a = tb + (wm * 64 + mt * 16 + lr) * 64 + ksw;
                    ldsm_x4(a, ah[0], ah[1], ah[2], ah[3]);
                    ldsm_x4(a + G1_TSZ, al[0], al[1], al[2], al[3]);
                    #pragma unroll
                    for (int p = 0; p < 2; p++)
                        #pragma unroll
                        for (int q = 0; q < 2; q++) {
                            int nt = p * 2 + q;
                            mma16816(c[mt][nt], ah, bh[p][q], bh[p][q + 2]);
                            mma16816(c[mt][nt], ah, bl[p][q], bl[p][q + 2]);
                            mma16816(c[mt][nt], al, bh[p][q], bh[p][q + 2]);
                        }
                }
            }
        }
    }

    // ---- write scores ----
    int r0 = m0 + wm * 64 + (lane >> 2);
    int col = n0 + wn * 32 + (lane & 3) * 2;
    #pragma unroll
    for (int mt = 0; mt < 4; mt++)
        #pragma unroll
        for (int nt = 0; nt < 4; nt++) {
            size_t base = boff + (size_t)(r0 + mt * 16) * 1024 + col + nt * 8;
            *(float2*)(g_scores + base) = make_float2(c[mt][nt][0], c[mt][nt][1]);
            *(float2*)(g_scores + base + 8 * 1024) = make_float2(c[mt][nt][2], c[mt][nt][3]);
        }

    // ---- fused E^T epilogue: convert-transpose E block (d0=m0, k0=n0) -> g_et ----
    __syncthreads();
    {
        __half* ts = (__half*)smem;  // 64 x 65 halves scratch (staging region, dead now)
        int f4id = tid & 15, rr = tid >> 4;
        int lane5 = tid >> 5;
        #pragma unroll
        for (int sub = 0; sub < 4; sub++) {
            int d0 = m0 + (sub >> 1) * 64, k0 = n0 + (sub & 1) * 64;
            #pragma unroll
            for (int pass = 0; pass < 4; pass++) {
                int k = pass * 16 + rr;
                float4 v = *(const float4*)(E + boff + (size_t)(k0 + k) * 1024 + d0 + f4id * 4);
                __half* rp = ts + k * 65 + f4id * 4;
                rp[0] = __float2half_rn(v.x);
                rp[1] = __float2half_rn(v.y);
                rp[2] = __float2half_rn(v.z);
                rp[3] = __float2half_rn(v.w);
            }
            __syncthreads();
            #pragma unroll
            for (int pass = 0; pass < 8; pass++) {
                int dd = pass * 8 + lane5;
                int kk = lane * 2;
                __half2 o = __halves2half2(ts[kk * 65 + dd], ts[(kk + 1) * 65 + dd]);
                *(__half2*)(g_et + boff + (size_t)(d0 + dd) * 1024 + k0 + kk) = o;
            }
            __syncthreads();
        }
    }
}

// ============ softmax: warp-per-row, barrier-free ============

__global__ void __launch_bounds__(256)
softmax_kernel() {
    int warp = threadIdx.x >> 5, lane = threadIdx.x & 31;
    size_t row = (size_t)blockIdx.x * 8 + warp;
    const float4* p = (const float4*)(g_scores + (row << 10));

    float4 v[8];
    #pragma unroll
    for (int i = 0; i < 8; i++) v[i] = p[i * 32 + lane];

    float m = -1e30f;
    #pragma unroll
    for (int i = 0; i < 8; i++)
        m = fmaxf(m, fmaxf(fmaxf(v[i].x, v[i].y), fmaxf(v[i].z, v[i].w)));
    #pragma unroll
    for (int o = 16; o; o >>= 1) m = fmaxf(m, __shfl_xor_sync(0xffffffffu, m, o));

    float s = 0.f;
    #pragma unroll
    for (int i = 0; i < 8; i++) {
        v[i].x = __expf(v[i].x - m); v[i].y = __expf(v[i].y - m);
        v[i].z = __expf(v[i].z - m); v[i].w = __expf(v[i].w - m);
        s += (v[i].x + v[i].y) + (v[i].z + v[i].w);
    }
    #pragma unroll
    for (int o = 16; o; o >>= 1) s += __shfl_xor_sync(0xffffffffu, s, o);
    float inv = 1.0f / s;

    __half2* w = (__half2*)(g_w + (row << 10));
    #pragma unroll
    for (int i = 0; i < 8; i++) {
        int e4 = i * 32 + lane;
        w[e4 * 2]     = __floats2half2_rn(v[i].x * inv, v[i].y * inv);
        w[e4 * 2 + 1] = __floats2half2_rn(v[i].z * inv, v[i].w * inv);
    }
}

// ============ GEMM2: out = W @ V (fp16, k64, 3-slot; prefetch before MMA) ============

__device__ __forceinline__ void g2_load(uint32_t base, int tid, int kc,
                                        const __half* gA, const __half* gB) {
    #pragma unroll
    for (int i = 0; i < 4; i++) {
        int id = i * 256 + tid;
        int row = id >> 3, seg = id & 7;
        uint32_t off = row * G2_ROW + seg * 16;
        size_t go = (size_t)row * 1024 + kc * 64 + seg * 8;
        cp_async16(base + off, gA + go);
        cp_async16(base + G2_TILE + off, gB + go);
    }
    CP_COMMIT();
}

__global__ void __launch_bounds__(256, 2)
gemm2_kernel(float* __restrict__ O) {
    extern __shared__ char smem[];
    uint32_t sb = smem_u32(smem);
    int tid = threadIdx.x, wid = tid >> 5, lane = tid & 31;
    int wm = wid >> 2, wn = wid & 3;
    int b = blockIdx.z;
    int m0 = blockIdx.y << 7, n0 = blockIdx.x << 7;
    size_t boff = (size_t)b << 20;

    const __half* gA = g_w + boff + (size_t)m0 * 1024;
    const __half* gB = g_et + boff + (size_t)n0 * 1024;

    float c[4][4][4];
    #pragma unroll
    for (int i = 0; i < 4; i++)
        #pragma unroll
        for (int j = 0; j < 4; j++)
            #pragma unroll
            for (int k = 0; k < 4; k++) c[i][j][k] = 0.f;

    g2_load(sb + 0 * 2 * G2_TILE, tid, 0, gA, gB);
    g2_load(sb + 1 * 2 * G2_TILE, tid, 1, gA, gB);

    int lr = lane & 15;
    uint32_t lkoff = (lane >> 4) * 16;

    int slot = 0;
    for (int kc = 0; kc < 16; kc++) {
        if (kc < 15) { CP_WAIT(1); } else { CP_WAIT(0); }
        __syncthreads();

        if (kc + 2 < 16) {
            int ns = kc + 2 - ((kc + 2) / 3) * 3;  // (kc+2) % 3
            g2_load(sb + ns * 2 * G2_TILE, tid, kc + 2, gA, gB);
        }

        uint32_t abase = sb + slot * 2 * G2_TILE;
        #pragma unroll
        for (int ks = 0; ks < 4; ks++) {
            uint32_t koff = ks * 32 + lkoff;
            uint32_t ah[4][4], bh[2][4];
            #pragma unroll
            for (int mt = 0; mt < 4; mt++) {
                uint32_t a = abase + (wm * 64 + mt * 16 + lr) * G2_ROW + koff;
                ldsm_x4(a, ah[mt][0], ah[mt][1], ah[mt][2], ah[mt][3]);
            }
            #pragma unroll
            for (int p = 0; p < 2; p++) {
                uint32_t a = abase + G2_TILE + (wn * 32 + p * 16 + lr) * G2_ROW + koff;
                ldsm_x4(a, bh[p][0], bh[p][1], bh[p][2], bh[p][3]);
            }
            #pragma unroll
            for (int mt = 0; mt < 4; mt++)
                #pragma unroll
                for (int p = 0; p < 2; p++)
                    #pragma unroll
                    for (int q = 0; q < 2; q++)
                        mma16816(c[mt][p * 2 + q], ah[mt], bh[p][q], bh[p][q + 2]);
        }

        slot = (slot == 2) ? 0 : slot + 1;
    }

    int r0 = m0 + wm * 64 + (lane >> 2);
    int col = n0 + wn * 32 + (lane & 3) * 2;
    #pragma unroll
    for (int mt = 0; mt < 4; mt++)
        #pragma unroll
        for (int nt = 0; nt < 4; nt++) {
            size_t base = boff + (size_t)(r0 + mt * 16) * 1024 + col + nt * 8;
            *(float2*)(O + base) = make_float2(c[mt][nt][0], c[mt][nt][1]);
            *(float2*)(O + base + 8 * 1024) = make_float2(c[mt][nt][2], c[mt][nt][3]);
        }
}

// ============ launcher ============

extern "C" void kernel_launch(void* const* d_in, const int* in_sizes, int n_in,
                              void* d_out, int out_size) {
    const float* dec = (const float*)d_in[0];   // decoder_hidden  [16,1024,1024]
    const float* enc = (const float*)d_in[1];   // encoder_outputs [16,1024,1024]
    float* out = (float*)d_out;

    cudaFuncSetAttribute(gemm1_kernel, cudaFuncAttributeMaxDynamicSharedMemorySize, G1_SMEM);
    cudaFuncSetAttribute(gemm2_kernel, cudaFuncAttributeMaxDynamicSharedMemorySize, G2_SMEM);

    gemm1_kernel<<<dim3(8, 8, 16), 256, G1_SMEM>>>(dec, enc);
    softmax_kernel<<<2048, 256>>>();
    gemm2_kernel<<<dim3(8, 8, 16), 256, G2_SMEM>>>(out);
}

// round 15
// speedup vs baseline: 1.1239x; 1.1239x over previous
#include <cuda_runtime.h>
#include <cuda_fp16.h>
#include <cstdint>

// ============ helpers ============

__device__ __forceinline__ uint32_t smem_u32(const void* p) {
    uint32_t a;
    asm("{ .reg .u64 t; cvta.to.shared.u64 t, %1; cvt.u32.u64 %0, t; }" : "=r"(a) : "l"(p));
    return a;
}

__device__ __forceinline__ void cp_async16(uint32_t saddr, const void* gaddr) {
    asm volatile("cp.async.cg.shared.global [%0], [%1], 16;" :: "r"(saddr), "l"(gaddr));
}
#define CP_COMMIT() asm volatile("cp.async.commit_group;" ::: "memory")
#define CP_WAIT(N)  asm volatile("cp.async.wait_group %0;" :: "n"(N) : "memory")

__device__ __forceinline__ void ldsm_x4(uint32_t addr, uint32_t& r0, uint32_t& r1,
                                        uint32_t& r2, uint32_t& r3) {
    asm volatile("ldmatrix.sync.aligned.m8n8.x4.shared.b16 {%0,%1,%2,%3}, [%4];"
                 : "=r"(r0), "=r"(r1), "=r"(r2), "=r"(r3) : "r"(addr));
}

__device__ __forceinline__ void lds128(uint32_t addr, uint32_t& x, uint32_t& y,
                                       uint32_t& z, uint32_t& w) {
    asm volatile("ld.shared.v4.b32 {%0,%1,%2,%3}, [%4];"
                 : "=r"(x), "=r"(y), "=r"(z), "=r"(w) : "r"(addr));
}
__device__ __forceinline__ void sts128(uint32_t a, uint32_t x, uint32_t y, uint32_t z, uint32_t w) {
    asm volatile("st.shared.v4.b32 [%0], {%1,%2,%3,%4};"
                 :: "r"(a), "r"(x), "r"(y), "r"(z), "r"(w) : "memory");
}

__device__ __forceinline__ void mma16816(float* c, const uint32_t* a, uint32_t b0, uint32_t b1) {
    asm volatile(
        "mma.sync.aligned.m16n8k16.row.col.f32.f16.f16.f32 "
        "{%0,%1,%2,%3}, {%4,%5,%6,%7}, {%8,%9}, {%0,%1,%2,%3};"
        : "+f"(c[0]), "+f"(c[1]), "+f"(c[2]), "+f"(c[3])
        : "r"(a[0]), "r"(a[1]), "r"(a[2]), "r"(a[3]), "r"(b0), "r"(b1));
}

__device__ __forceinline__ void split2(float v0, float v1, uint32_t& hi, uint32_t& lo) {
    __half h0 = __float2half_rn(v0), h1 = __float2half_rn(v1);
    __half2 hh = __halves2half2(h0, h1);
    hi = *(uint32_t*)&hh;
    __half2 ll = __floats2half2_rn(v0 - __half2float(h0), v1 - __half2float(h1));
    lo = *(uint32_t*)&ll;
}

// ============ device scratch ============

static constexpr size_t NEL = 16ull * 1024 * 1024;  // 16 x 1024 x 1024

__device__ __half g_w[NEL];     // softmax weights, fp16
__device__ __half g_et[NEL];    // E^T per batch, fp16: [b][d][k]
__device__ float  g_scores[NEL];

// gemm1 fp16 MMA tile: 128 rows x 32 halves, stride 80 B (conflict-free)
static constexpr int ROWB = 80;
static constexpr int TILEB = 128 * ROWB;  // 10240 B

// ---- GEMM1 smem layout (k32, single staging + single tiles; R5/R13-proven) ----
static constexpr int G1_ROW32 = 144;
static constexpr int G1_STG   = 128 * G1_ROW32;      // 18432 B per operand
static constexpr int G1_SA    = 0;
static constexpr int G1_SB    = G1_STG;
static constexpr int G1_TQH   = 2 * G1_STG;
static constexpr int G1_TQL   = G1_TQH + TILEB;
static constexpr int G1_TEH   = G1_TQH + 2 * TILEB;
static constexpr int G1_TEL   = G1_TQH + 3 * TILEB;
static constexpr int G1_SMEM  = G1_TQH + 4 * TILEB;  // 77824 B

// ---- GEMM2 smem layout (k64, 3-slot rotation; R10-proven) ----
static constexpr int G2_ROW  = 144;
static constexpr int G2_TILE = 128 * G2_ROW;         // 18432 B per operand
static constexpr int G2_SMEM = 3 * 2 * G2_TILE;      // 110592 B

// ============ GEMM1: scores = Q @ E^T, convert-in-kernel, 3-term split ============
// Epilogue: each CTA also convert-transposes its (d0=m0, k0=n0) 128x128 E block -> g_et.

__device__ __forceinline__ void g1_cp(uint32_t sb, int tid, int kc,
                                      const float* gQ, const float* gE) {
    #pragma unroll
    for (int i = 0; i < 4; i++) {
        int id = i * 256 + tid;           // 0..1023
        int row = id >> 3, seg = id & 7;
        uint32_t off = row * G1_ROW32 + seg * 16;
        size_t go = (size_t)row * 1024 + kc * 32 + seg * 4;
        cp_async16(sb + G1_SA + off, gQ + go);
        cp_async16(sb + G1_SB + off, gE + go);
    }
    CP_COMMIT();
}

__global__ void __launch_bounds__(256, 2)
gemm1_kernel(const float* __restrict__ Q, const float* __restrict__ E) {
    extern __shared__ char smem[];
    uint32_t sb = smem_u32(smem);
    int tid = threadIdx.x, wid = tid >> 5, lane = tid & 31;
    int wm = wid >> 2, wn = wid & 3;
    int b = blockIdx.z;
    int m0 = blockIdx.y << 7, n0 = blockIdx.x << 7;
    size_t boff = (size_t)b << 20;

    const float* gQ = Q + boff + (size_t)m0 * 1024;
    const float* gE = E + boff + (size_t)n0 * 1024;

    float c[4][4][4];
    #pragma unroll
    for (int i = 0; i < 4; i++)
        #pragma unroll
        for (int j = 0; j < 4; j++)
            #pragma unroll
            for (int k = 0; k < 4; k++) c[i][j][k] = 0.f;

    g1_cp(sb, tid, 0, gQ, gE);

    int lr = lane & 15;
    uint32_t lkoff = (lane >> 4) * 16;  // bytes

    int cm = tid >> 1;
    int cko = (tid & 1) * 16;
    uint32_t csrc = cm * G1_ROW32 + cko * 4;
    uint32_t cdst = cm * 80 + cko * 2;

    for (int kc = 0; kc < 32; kc++) {
        CP_WAIT(0);
        __syncthreads();   // staging(kc) ready; MMA(kc-1) done -> tiles reusable

        // ---- convert staging -> fp16 hi/lo tiles ----
        {
            uint32_t ra[4][4], rb[4][4];
            #pragma unroll
            for (int j = 0; j < 4; j++)
                lds128(sb + G1_SA + csrc + j * 16, ra[j][0], ra[j][1], ra[j][2], ra[j][3]);
            #pragma unroll
            for (int j = 0; j < 4; j++)
                lds128(sb + G1_SB + csrc + j * 16, rb[j][0], rb[j][1], rb[j][2], rb[j][3]);

            uint32_t hi[8], lo[8];
            #pragma unroll
            for (int j = 0; j < 4; j++) {
                split2(__uint_as_float(ra[j][0]), __uint_as_float(ra[j][1]), hi[j * 2], lo[j * 2]);
                split2(__uint_as_float(ra[j][2]), __uint_as_float(ra[j][3]), hi[j * 2 + 1], lo[j * 2 + 1]);
            }
            sts128(sb + G1_TQH + cdst,      hi[0], hi[1], hi[2], hi[3]);
            sts128(sb + G1_TQH + cdst + 16, hi[4], hi[5], hi[6], hi[7]);
            sts128(sb + G1_TQL + cdst,      lo[0], lo[1], lo[2], lo[3]);
            sts128(sb + G1_TQL + cdst + 16, lo[4], lo[5], lo[6], lo[7]);
            #pragma unroll
            for (int j = 0; j < 4; j++) {
                split2(__uint_as_float(rb[j][0]), __uint_as_float(rb[j][1]), hi[j * 2], lo[j * 2]);
                split2(__uint_as_float(rb[j][2]), __uint_as_float(rb[j][3]), hi[j * 2 + 1], lo[j * 2 + 1]);
            }
            sts128(sb + G1_TEH + cdst,      hi[0], hi[1], hi[2], hi[3]);
            sts128(sb + G1_TEH + cdst + 16, hi[4], hi[5], hi[6], hi[7]);
            sts128(sb + G1_TEL + cdst,      lo[0], lo[1], lo[2], lo[3]);
            sts128(sb + G1_TEL + cdst + 16, lo[4], lo[5], lo[6], lo[7]);
        }
        __syncthreads();   // tiles ready; staging free for next cp

        if (kc + 1 < 32) g1_cp(sb, tid, kc + 1, gQ, gE);

        // ---- MMA phase ----
        #pragma unroll
        for (int ks = 0; ks < 2; ks++) {
            uint32_t koff = ks * 32 + lkoff;
            uint32_t bh[2][4], bl[2][4];
            #pragma unroll
            for (int p = 0; p < 2; p++) {
                uint32_t a = sb + G1_TEH + (wn * 32 + p * 16 + lr) * ROWB + koff;
                ldsm_x4(a, bh[p][0], bh[p][1], bh[p][2], bh[p][3]);
                ldsm_x4(a + TILEB, bl[p][0], bl[p][1], bl[p][2], bl[p][3]);
            }
            #pragma unroll
            for (int mt = 0; mt < 4; mt++) {
                uint32_t ah[4], al[4];
                uint32_t a = sb + G1_TQH + (wm * 64 + mt * 16 + lr) * ROWB + koff;
                ldsm_x4(a, ah[0], ah[1], ah[2], ah[3]);
                ldsm_x4(a + TILEB, al[0], al[1], al[2], al[3]);
                #pragma unroll
                for (int p = 0; p < 2; p++)
                    #pragma unroll
                    for (int q = 0; q < 2; q++) {
                        int nt = p * 2 + q;
                        mma16816(c[mt][nt], ah, bh[p][q], bh[p][q + 2]);
                        mma16816(c[mt][nt], ah, bl[p][q], bl[p][q + 2]);
                        mma16816(c[mt][nt], al, bh[p][q], bh[p][q + 2]);
                    }
            }
        }
    }

    // ---- write scores (streaming: single-use, keep L2 for Q/E) ----
    int r0 = m0 + wm * 64 + (lane >> 2);
    int col = n0 + wn * 32 + (lane & 3) * 2;
    #pragma unroll
    for (int mt = 0; mt < 4; mt++)
        #pragma unroll
        for (int nt = 0; nt < 4; nt++) {
            size_t base = boff + (size_t)(r0 + mt * 16) * 1024 + col + nt * 8;
            __stcs((float2*)(g_scores + base), make_float2(c[mt][nt][0], c[mt][nt][1]));
            __stcs((float2*)(g_scores + base + 8 * 1024), make_float2(c[mt][nt][2], c[mt][nt][3]));
        }

    // ---- fused E^T epilogue: convert-transpose E block (d0=m0, k0=n0) -> g_et ----
    __syncthreads();                 // last MMA's LDSM reads done; smem reusable
    {
        __half* ts = (__half*)smem;  // 64 x 65 halves scratch
        int f4id = tid & 15, rr = tid >> 4;
        int lane5 = tid >> 5;
        #pragma unroll
        for (int sub = 0; sub < 4; sub++) {
            int d0 = m0 + (sub >> 1) * 64, k0 = n0 + (sub & 1) * 64;
            #pragma unroll
            for (int pass = 0; pass < 4; pass++) {
                int k = pass * 16 + rr;
                float4 v = *(const float4*)(E + boff + (size_t)(k0 + k) * 1024 + d0 + f4id * 4);
                __half* rp = ts + k * 65 + f4id * 4;
                rp[0] = __float2half_rn(v.x);
                rp[1] = __float2half_rn(v.y);
                rp[2] = __float2half_rn(v.z);
                rp[3] = __float2half_rn(v.w);
            }
            __syncthreads();
            #pragma unroll
            for (int pass = 0; pass < 8; pass++) {
                int dd = pass * 8 + lane5;
                int kk = lane * 2;
                __half2 o = __halves2half2(ts[kk * 65 + dd], ts[(kk + 1) * 65 + dd]);
                *(__half2*)(g_et + boff + (size_t)(d0 + dd) * 1024 + k0 + kk) = o;
            }
            __syncthreads();
        }
    }
}

// ============ softmax: warp-per-row, barrier-free, streaming score reads ============

__global__ void __launch_bounds__(256)
softmax_kernel() {
    int warp = threadIdx.x >> 5, lane = threadIdx.x & 31;
    size_t row = (size_t)blockIdx.x * 8 + warp;
    const float4* p = (const float4*)(g_scores + (row << 10));

    float4 v[8];
    #pragma unroll
    for (int i = 0; i < 8; i++) v[i] = __ldcs(p + i * 32 + lane);

    float m = -1e30f;
    #pragma unroll
    for (int i = 0; i < 8; i++)
        m = fmaxf(m, fmaxf(fmaxf(v[i].x, v[i].y), fmaxf(v[i].z, v[i].w)));
    #pragma unroll
    for (int o = 16; o; o >>= 1) m = fmaxf(m, __shfl_xor_sync(0xffffffffu, m, o));

    float s = 0.f;
    #pragma unroll
    for (int i = 0; i < 8; i++) {
        v[i].x = __expf(v[i].x - m); v[i].y = __expf(v[i].y - m);
        v[i].z = __expf(v[i].z - m); v[i].w = __expf(v[i].w - m);
        s += (v[i].x + v[i].y) + (v[i].z + v[i].w);
    }
    #pragma unroll
    for (int o = 16; o; o >>= 1) s += __shfl_xor_sync(0xffffffffu, s, o);
    float inv = 1.0f / s;

    __half2* w = (__half2*)(g_w + (row << 10));
    #pragma unroll
    for (int i = 0; i < 8; i++) {
        int e4 = i * 32 + lane;
        w[e4 * 2]     = __floats2half2_rn(v[i].x * inv, v[i].y * inv);
        w[e4 * 2 + 1] = __floats2half2_rn(v[i].z * inv, v[i].w * inv);
    }
}

// ============ GEMM2: out = W @ V (fp16, k64, 3-slot; prefetch before MMA) ============

__device__ __forceinline__ void g2_load(uint32_t base, int tid, int kc,
                                        const __half* gA, const __half* gB) {
    #pragma unroll
    for (int i = 0; i < 4; i++) {
        int id = i * 256 + tid;
        int row = id >> 3, seg = id & 7;
        uint32_t off = row * G2_ROW + seg * 16;
        size_t go = (size_t)row * 1024 + kc * 64 + seg * 8;
        cp_async16(base + off, gA + go);
        cp_async16(base + G2_TILE + off, gB + go);
    }
    CP_COMMIT();
}

__global__ void __launch_bounds__(256, 2)
gemm2_kernel(float* __restrict__ O) {
    extern __shared__ char smem[];
    uint32_t sb = smem_u32(smem);
    int tid = threadIdx.x, wid = tid >> 5, lane = tid & 31;
    int wm = wid >> 2, wn = wid & 3;
    int b = blockIdx.z;
    int m0 = blockIdx.y << 7, n0 = blockIdx.x << 7;
    size_t boff = (size_t)b << 20;

    const __half* gA = g_w + boff + (size_t)m0 * 1024;
    const __half* gB = g_et + boff + (size_t)n0 * 1024;

    float c[4][4][4];
    #pragma unroll
    for (int i = 0; i < 4; i++)
        #pragma unroll
        for (int j = 0; j < 4; j++)
            #pragma unroll
            for (int k = 0; k < 4; k++) c[i][j][k] = 0.f;

    g2_load(sb + 0 * 2 * G2_TILE, tid, 0, gA, gB);
    g2_load(sb + 1 * 2 * G2_TILE, tid, 1, gA, gB);

    int lr = lane & 15;
    uint32_t lkoff = (lane >> 4) * 16;

    int slot = 0;
    for (int kc = 0; kc < 16; kc++) {
        if (kc < 15) { CP_WAIT(1); } else { CP_WAIT(0); }
        __syncthreads();

        if (kc + 2 < 16) {
            int ns = kc + 2 - ((kc + 2) / 3) * 3;  // (kc+2) % 3
            g2_load(sb + ns * 2 * G2_TILE, tid, kc + 2, gA, gB);
        }

        uint32_t abase = sb + slot * 2 * G2_TILE;
        #pragma unroll
        for (int ks = 0; ks < 4; ks++) {
            uint32_t koff = ks * 32 + lkoff;
            uint32_t ah[4][4], bh[2][4];
            #pragma unroll
            for (int mt = 0; mt < 4; mt++) {
                uint32_t a = abase + (wm * 64 + mt * 16 + lr) * G2_ROW + koff;
                ldsm_x4(a, ah[mt][0], ah[mt][1], ah[mt][2], ah[mt][3]);
            }
            #pragma unroll
            for (int p = 0; p < 2; p++) {
                uint32_t a = abase + G2_TILE + (wn * 32 + p * 16 + lr) * G2_ROW + koff;
                ldsm_x4(a, bh[p][0], bh[p][1], bh[p][2], bh[p][3]);
            }
            #pragma unroll
            for (int mt = 0; mt < 4; mt++)
                #pragma unroll
                for (int p = 0; p < 2; p++)
                    #pragma unroll
                    for (int q = 0; q < 2; q++)
                        mma16816(c[mt][p * 2 + q], ah[mt], bh[p][q], bh[p][q + 2]);
        }

        slot = (slot == 2) ? 0 : slot + 1;
    }

    // streaming output stores: O never re-read; keep L2 for g_w/g_et
    int r0 = m0 + wm * 64 + (lane >> 2);
    int col = n0 + wn * 32 + (lane & 3) * 2;
    #pragma unroll
    for (int mt = 0; mt < 4; mt++)
        #pragma unroll
        for (int nt = 0; nt < 4; nt++) {
            size_t base = boff + (size_t)(r0 + mt * 16) * 1024 + col + nt * 8;
            __stcs((float2*)(O + base), make_float2(c[mt][nt][0], c[mt][nt][1]));
            __stcs((float2*)(O + base + 8 * 1024), make_float2(c[mt][nt][2], c[mt][nt][3]));
        }
}

// ============ launcher ============

extern "C" void kernel_launch(void* const* d_in, const int* in_sizes, int n_in,
                              void* d_out, int out_size) {
    const float* dec = (const float*)d_in[0];   // decoder_hidden  [16,1024,1024]
    const float* enc = (const float*)d_in[1];   // encoder_outputs [16,1024,1024]
    float* out = (float*)d_out;

    cudaFuncSetAttribute(gemm1_kernel, cudaFuncAttributeMaxDynamicSharedMemorySize, G1_SMEM);
    cudaFuncSetAttribute(gemm2_kernel, cudaFuncAttributeMaxDynamicSharedMemorySize, G2_SMEM);

    gemm1_kernel<<<dim3(8, 8, 16), 256, G1_SMEM>>>(dec, enc);
    softmax_kernel<<<2048, 256>>>();
    gemm2_kernel<<<dim3(8, 8, 16), 256, G2_SMEM>>>(out);
}